// round 2
// baseline (speedup 1.0000x reference)
#include <cuda_runtime.h>
#include <cuda_bf16.h>
#include <cstdint>

#define IN_F   4096
#define OUT_F  11008
#define GS     128
#define MROWS  8192   // BATCH * SEQ = 4 * 2048

// Tile config: 128x128 block tile, K-tile 16, 256 threads, 8x8 per-thread microtile.
constexpr int BM = 128;
constexpr int BN = 128;
constexpr int BK = 16;
constexpr int THREADS = 256;

__global__ __launch_bounds__(THREADS)
void gptq_gemm_kernel(const float* __restrict__ x,
                      const int*   __restrict__ qweight,
                      const int*   __restrict__ qzeros,
                      const float* __restrict__ scales,
                      float*       __restrict__ out)
{
    // +4 padding: keeps float4 alignment (stride % 4 == 0) and reduces bank conflicts.
    __shared__ float As[BK][BM + 4];   // As[k][m] : x tile, transposed
    __shared__ float Bs[BK][BN + 4];   // Bs[k][n] : dequantized W tile

    const int tid = threadIdx.x;
    const int tx  = tid % 16;          // 16 thread-cols
    const int ty  = tid / 16;          // 16 thread-rows
    const int n0  = blockIdx.x * BN;
    const int m0  = blockIdx.y * BM;

    // x-load mapping: 128 rows x 16 k-floats = 512 float4; 256 threads -> 2 each.
    const int kq   = tid % 4;          // which float4 along k (4 * 4 = 16 floats)
    const int mrow = tid / 4;          // 0..63 (second row = +64)

    // W-load mapping: BK=16 -> 2 packed int32 rows x 128 cols = 256 int32, 1/thread.
    const int oc   = tid % 128;        // output column within tile
    const int r8   = tid / 128;        // packed row (0..1), covers 8 input dims each
    const int ncol = n0 + oc;          // global output column

    float acc[8][8];
    #pragma unroll
    for (int i = 0; i < 8; ++i)
        #pragma unroll
        for (int j = 0; j < 8; ++j)
            acc[i][j] = 0.0f;

    for (int kt = 0; kt < IN_F / BK; ++kt) {
        const int k0 = kt * BK;

        // ---- load x tile (transposed into As) ----
        #pragma unroll
        for (int mm = 0; mm < 2; ++mm) {
            const int row = mrow + mm * 64;
            const float4 v = *reinterpret_cast<const float4*>(
                &x[(size_t)(m0 + row) * IN_F + k0 + kq * 4]);
            As[kq * 4 + 0][row] = v.x;
            As[kq * 4 + 1][row] = v.y;
            As[kq * 4 + 2][row] = v.z;
            As[kq * 4 + 3][row] = v.w;
        }

        // ---- dequantize W tile into Bs ----
        {
            // BK=16 divides GS=128 -> the whole K-tile lives in one group.
            const int g = k0 / GS;
            const unsigned qw =
                (unsigned)qweight[(size_t)(k0 / 8 + r8) * OUT_F + ncol];
            const int z =
                ((qzeros[(size_t)g * (OUT_F / 8) + (ncol >> 3)] >> ((ncol & 7) * 4)) & 0xF) + 1;
            const float sc = scales[(size_t)g * OUT_F + ncol];
            #pragma unroll
            for (int j = 0; j < 8; ++j) {
                const int w = (int)((qw >> (4 * j)) & 0xF);
                Bs[r8 * 8 + j][oc] = (float)(w - z) * sc;
            }
        }

        __syncthreads();

        // ---- compute: 8x8 microtile per thread ----
        #pragma unroll
        for (int kk = 0; kk < BK; ++kk) {
            float a[8], b[8];
            *reinterpret_cast<float4*>(&a[0]) =
                *reinterpret_cast<const float4*>(&As[kk][ty * 4]);
            *reinterpret_cast<float4*>(&a[4]) =
                *reinterpret_cast<const float4*>(&As[kk][64 + ty * 4]);
            *reinterpret_cast<float4*>(&b[0]) =
                *reinterpret_cast<const float4*>(&Bs[kk][tx * 4]);
            *reinterpret_cast<float4*>(&b[4]) =
                *reinterpret_cast<const float4*>(&Bs[kk][64 + tx * 4]);
            #pragma unroll
            for (int i = 0; i < 8; ++i)
                #pragma unroll
                for (int j = 0; j < 8; ++j)
                    acc[i][j] = fmaf(a[i], b[j], acc[i][j]);
        }

        __syncthreads();
    }

    // ---- write output (split microtile: rows ty*4..+3 and 64+ty*4..+3) ----
    #pragma unroll
    for (int i = 0; i < 8; ++i) {
        const int row = m0 + ((i < 4) ? (ty * 4 + i) : (64 + ty * 4 + (i - 4)));
        float4 v0, v1;
        v0.x = acc[i][0]; v0.y = acc[i][1]; v0.z = acc[i][2]; v0.w = acc[i][3];
        v1.x = acc[i][4]; v1.y = acc[i][5]; v1.z = acc[i][6]; v1.w = acc[i][7];
        *reinterpret_cast<float4*>(&out[(size_t)row * OUT_F + n0 + tx * 4])      = v0;
        *reinterpret_cast<float4*>(&out[(size_t)row * OUT_F + n0 + 64 + tx * 4]) = v1;
    }
}

extern "C" void kernel_launch(void* const* d_in, const int* in_sizes, int n_in,
                              void* d_out, int out_size)
{
    const float* x       = (const float*)d_in[0];
    const int*   qweight = (const int*)  d_in[1];
    const int*   qzeros  = (const int*)  d_in[2];
    const float* scales  = (const float*)d_in[3];
    float*       out     = (float*)d_out;

    dim3 grid(OUT_F / BN, MROWS / BM);   // 86 x 64
    gptq_gemm_kernel<<<grid, THREADS>>>(x, qweight, qzeros, scales, out);
}

// round 7
// speedup vs baseline: 6.1847x; 6.1847x over previous
#include <cuda_runtime.h>
#include <cuda_fp16.h>
#include <cstdint>

#define IN_F   4096
#define OUT_F  11008
#define GS     128
#define MROWS  8192

constexpr int BM = 128;
constexpr int BN = 128;
constexpr int BK = 32;               // k per chunk (fp16 elements)
constexpr int KPAD = 40;             // padded k stride (80B) -> conflict-free ldmatrix
constexpr int THREADS = 256;
constexpr int NC = IN_F / BK;        // 128 chunks

__device__ __forceinline__ uint32_t f22h2(float a, float b) {
    __half2 h = __floats2half2_rn(a, b);
    return reinterpret_cast<uint32_t&>(h);
}

__device__ __forceinline__ void ldm_x4(uint32_t& r0, uint32_t& r1,
                                       uint32_t& r2, uint32_t& r3, uint32_t addr) {
    asm volatile("ldmatrix.sync.aligned.m8n8.x4.shared.b16 {%0,%1,%2,%3}, [%4];"
                 : "=r"(r0), "=r"(r1), "=r"(r2), "=r"(r3) : "r"(addr));
}

__device__ __forceinline__ void mma16816(float* d, const uint32_t* a, const uint32_t* b) {
    asm volatile("mma.sync.aligned.m16n8k16.row.col.f32.f16.f16.f32 "
                 "{%0,%1,%2,%3}, {%4,%5,%6,%7}, {%8,%9}, {%0,%1,%2,%3};"
                 : "+f"(d[0]), "+f"(d[1]), "+f"(d[2]), "+f"(d[3])
                 : "r"(a[0]), "r"(a[1]), "r"(a[2]), "r"(a[3]),
                   "r"(b[0]), "r"(b[1]));
}

__global__ __launch_bounds__(THREADS, 2)
void gptq_mma_kernel(const float* __restrict__ x,
                     const int*   __restrict__ qweight,
                     const int*   __restrict__ qzeros,
                     const float* __restrict__ scales,
                     float*       __restrict__ out)
{
    // k within each 8-group is stored permuted: pos(j) = (j&3)*2 + (j>>2),
    // applied identically to A and B (dot-product invariant).
    __shared__ __align__(16) __half A_s[2][BM][KPAD];
    __shared__ __align__(16) __half B_s[2][BN][KPAD];

    const int tid = threadIdx.x;
    const int lid = tid & 31;
    const int wid = tid >> 5;
    const int wm  = wid & 3;           // warp row (32 rows)
    const int wn  = wid >> 2;          // warp col (64 cols)
    const int m0  = blockIdx.y * BM;
    const int n0  = blockIdx.x * BN;

    // ---- producer thread mappings ----
    // A: 128 rows x 4 k-groups = 512 tasks, 2/thread. task -> row=task>>2, grp=task&3.
    // B: 4 packed rows x 128 cols = 512 int32, 2/thread.
    const int oc   = tid & 127;
    const int r8a  = tid >> 7;         // 0/1; second int32 at +2
    const int ncol = n0 + oc;
    const int zsh  = (oc & 7) * 4;

    const uint32_t aBase = (uint32_t)__cvta_generic_to_shared(&A_s[0][0][0]);
    const uint32_t bBase = (uint32_t)__cvta_generic_to_shared(&B_s[0][0][0]);
    constexpr uint32_t STG_BYTES = BM * KPAD * 2;   // 10240 per stage per array

    float4 xr[4];
    int    wq[2];
    int    zw;
    float  sc;

    float acc[2][8][4];
    #pragma unroll
    for (int i = 0; i < 2; ++i)
        #pragma unroll
        for (int j = 0; j < 8; ++j)
            #pragma unroll
            for (int q = 0; q < 4; ++q) acc[i][j][q] = 0.0f;

    auto load_regs = [&](int kt) {
        const int k0 = kt * BK;
        #pragma unroll
        for (int i = 0; i < 2; ++i) {
            const int task = i * 256 + tid;
            const int row = task >> 2, grp = task & 3;
            const float* p = &x[(size_t)(m0 + row) * IN_F + k0 + grp * 8];
            xr[i * 2 + 0] = *reinterpret_cast<const float4*>(p);
            xr[i * 2 + 1] = *reinterpret_cast<const float4*>(p + 4);
        }
        const int g = k0 / GS;
        zw = qzeros[(size_t)g * (OUT_F / 8) + (ncol >> 3)];
        sc = scales[(size_t)g * OUT_F + ncol];
        wq[0] = qweight[(size_t)(k0 / 8 + r8a) * OUT_F + ncol];
        wq[1] = qweight[(size_t)(k0 / 8 + r8a + 2) * OUT_F + ncol];
    };

    auto store_smem = [&](int st) {
        // A: 8 floats -> permuted fp16 pairs (j, j+4) -> one uint4 per task
        #pragma unroll
        for (int i = 0; i < 2; ++i) {
            const int task = i * 256 + tid;
            const int row = task >> 2, grp = task & 3;
            const float4 v0 = xr[i * 2 + 0];
            const float4 v1 = xr[i * 2 + 1];
            uint4 u;
            u.x = f22h2(v0.x, v1.x);   // (j0, j4)
            u.y = f22h2(v0.y, v1.y);   // (j1, j5)
            u.z = f22h2(v0.z, v1.z);   // (j2, j6)
            u.w = f22h2(v0.w, v1.w);   // (j3, j7)
            *reinterpret_cast<uint4*>(&A_s[st][row][grp * 8]) = u;
        }
        // B: lop3 nibble->fp16 (1024+w), exact hsub2 of (1024+z), hmul2 by s
        const float zf = (float)(((zw >> zsh) & 0xF) + 1 + 1024);
        const __half2 z2 = __floats2half2_rn(zf, zf);
        const __half2 s2 = __floats2half2_rn(sc, sc);
        #pragma unroll
        for (int p = 0; p < 2; ++p) {
            const uint32_t q = (uint32_t)wq[p];
            uint4 u;
            uint32_t t;
            __half2 hv, r;
            t = (q & 0x000F000Fu) | 0x64006400u;
            hv = reinterpret_cast<__half2&>(t);
            r = __hmul2(__hsub2(hv, z2), s2);  u.x = reinterpret_cast<uint32_t&>(r);
            t = ((q >> 4) & 0x000F000Fu) | 0x64006400u;
            hv = reinterpret_cast<__half2&>(t);
            r = __hmul2(__hsub2(hv, z2), s2);  u.y = reinterpret_cast<uint32_t&>(r);
            t = ((q >> 8) & 0x000F000Fu) | 0x64006400u;
            hv = reinterpret_cast<__half2&>(t);
            r = __hmul2(__hsub2(hv, z2), s2);  u.z = reinterpret_cast<uint32_t&>(r);
            t = ((q >> 12) & 0x000F000Fu) | 0x64006400u;
            hv = reinterpret_cast<__half2&>(t);
            r = __hmul2(__hsub2(hv, z2), s2);  u.w = reinterpret_cast<uint32_t&>(r);
            *reinterpret_cast<uint4*>(&B_s[st][oc][(r8a + p * 2) * 8]) = u;
        }
    };

    auto compute = [&](int st) {
        const uint32_t aS = aBase + (uint32_t)st * STG_BYTES;
        const uint32_t bS = bBase + (uint32_t)st * STG_BYTES;
        #pragma unroll
        for (int ks = 0; ks < 2; ++ks) {
            uint32_t af[2][4];
            #pragma unroll
            for (int ma = 0; ma < 2; ++ma) {
                const int row = wm * 32 + ma * 16 + (lid & 15);
                const int col = ks * 16 + (lid >> 4) * 8;
                ldm_x4(af[ma][0], af[ma][1], af[ma][2], af[ma][3],
                       aS + (uint32_t)(row * KPAD + col) * 2);
            }
            uint32_t bf[8][2];
            #pragma unroll
            for (int g4 = 0; g4 < 4; ++g4) {
                const int row = wn * 64 + g4 * 16 + ((lid >> 4) & 1) * 8 + (lid & 7);
                const int col = ks * 16 + ((lid >> 3) & 1) * 8;
                uint32_t r0, r1, r2, r3;
                ldm_x4(r0, r1, r2, r3, bS + (uint32_t)(row * KPAD + col) * 2);
                bf[g4 * 2 + 0][0] = r0; bf[g4 * 2 + 0][1] = r1;
                bf[g4 * 2 + 1][0] = r2; bf[g4 * 2 + 1][1] = r3;
            }
            #pragma unroll
            for (int ma = 0; ma < 2; ++ma)
                #pragma unroll
                for (int na = 0; na < 8; ++na)
                    mma16816(acc[ma][na], af[ma], bf[na]);
        }
    };

    // ---- pipeline ----
    load_regs(0);
    store_smem(0);
    __syncthreads();

    for (int kt = 0; kt < NC; ++kt) {
        if (kt + 1 < NC) load_regs(kt + 1);
        compute(kt & 1);
        if (kt + 1 < NC) store_smem((kt + 1) & 1);
        __syncthreads();
    }

    // ---- epilogue ----
    #pragma unroll
    for (int ma = 0; ma < 2; ++ma) {
        const int row = m0 + wm * 32 + ma * 16 + (lid >> 2);
        #pragma unroll
        for (int na = 0; na < 8; ++na) {
            const int col = n0 + wn * 64 + na * 8 + (lid & 3) * 2;
            float2 v01, v23;
            v01.x = acc[ma][na][0]; v01.y = acc[ma][na][1];
            v23.x = acc[ma][na][2]; v23.y = acc[ma][na][3];
            *reinterpret_cast<float2*>(&out[(size_t)row * OUT_F + col]) = v01;
            *reinterpret_cast<float2*>(&out[(size_t)(row + 8) * OUT_F + col]) = v23;
        }
    }
}

extern "C" void kernel_launch(void* const* d_in, const int* in_sizes, int n_in,
                              void* d_out, int out_size)
{
    const float* x       = (const float*)d_in[0];
    const int*   qweight = (const int*)  d_in[1];
    const int*   qzeros  = (const int*)  d_in[2];
    const float* scales  = (const float*)d_in[3];
    float*       out     = (float*)d_out;

    dim3 grid(OUT_F / BN, MROWS / BM);   // 86 x 64
    gptq_mma_kernel<<<grid, THREADS>>>(x, qweight, qzeros, scales, out);
}